// round 2
// baseline (speedup 1.0000x reference)
#include <cuda_runtime.h>

#define BB   2
#define CFI  32
#define HH   192
#define WWD  192
#define NN   (HH*WWD)        // 36864
#define NUMK 16
#define CT   67
#define EPSL 1e-5f
#define TS   256
#define NT   (NN/TS)         // 144

// ---------------- scratch (static device globals; no allocation) ----------------
__device__ float g_P[BB*NN*CFI];        // [b][n][c]  folded W1[:,0:32] @ If
__device__ float g_Q[BB*NN*CFI];        // [b][n][c]  folded W1[:,32:64] @ If
__device__ float g_U[BB*NUMK*NN];       // (Alpha+1)*Pfnum + Beta
__device__ float g_Om[BB*NUMK*NN];      // Omega logits

__device__ float g_WPQ[64*32];          // rows 0..31: P weights, 32..63: Q weights (BN-folded)
__device__ float g_w1p[32], g_w1a[32], g_w1b[32], g_t1[32];
// duplicated-pair weights: [kk][c][2] with both entries = W[c][kk]*inv (BN-folded)
__device__ float g_W2d[32*32*2], g_t2[32];
__device__ float g_W3d[32*32*2], g_t3[32];
__device__ float g_W4d[32*32*2], g_t4[32];
__device__ float g_wcA[32], g_wcB[32], g_wcC[32];
__device__ float g_bcv[3];
__device__ int   g_args64;              // 1 if args buffer is int64, 0 if int32

// ---------------- packed f32x2 helpers (Blackwell FFMA2 path) ----------------
__device__ __forceinline__ float2 fma2(float2 a, float2 b, float2 c) {
    float2 r;
    asm("fma.rn.f32x2 %0, %1, %2, %3;"
        : "=l"(*(unsigned long long*)&r)
        : "l"(*(const unsigned long long*)&a),
          "l"(*(const unsigned long long*)&b),
          "l"(*(const unsigned long long*)&c));
    return r;
}
__device__ __forceinline__ float2 mul2(float2 a, float2 b) {
    float2 r;
    asm("mul.rn.f32x2 %0, %1, %2;"
        : "=l"(*(unsigned long long*)&r)
        : "l"(*(const unsigned long long*)&a),
          "l"(*(const unsigned long long*)&b));
    return r;
}
__device__ __forceinline__ float2 add2(float2 a, float2 b) {
    float2 r;
    asm("add.rn.f32x2 %0, %1, %2;"
        : "=l"(*(unsigned long long*)&r)
        : "l"(*(const unsigned long long*)&a),
          "l"(*(const unsigned long long*)&b));
    return r;
}
__device__ __forceinline__ float2 abs2(float2 a) {
    unsigned long long u = (*(const unsigned long long*)&a) & 0x7FFFFFFF7FFFFFFFULL;
    return *(float2*)&u;
}
__device__ __forceinline__ float2 d2(float v) { return make_float2(v, v); }

__device__ __forceinline__ float frcp(float x) { float y; asm("rcp.approx.f32 %0, %1;" : "=f"(y) : "f"(x)); return y; }
__device__ __forceinline__ float fex2(float x) { float y; asm("ex2.approx.f32 %0, %1;" : "=f"(y) : "f"(x)); return y; }

// gelu on a pair: 0.5*(x + |x|*erf(|x|/sqrt2)), erf via A&S 7.1.26 (|eps|<=1.5e-7)
__device__ __forceinline__ float2 gelu2(float2 x) {
    float2 ax = abs2(x);
    float2 z  = mul2(ax, d2(0.70710678118654752f));
    float2 q  = fma2(z, d2(0.3275911f), d2(1.0f));
    float2 t; t.x = frcp(q.x); t.y = frcp(q.y);
    float2 z2 = mul2(z, z);
    float2 s  = mul2(z2, d2(-1.4426950408889634f));
    float2 e; e.x = fex2(s.x); e.y = fex2(s.y);
    float2 h  = fma2(d2(1.061405429f), t, d2(-1.453152027f));
    h = fma2(h, t, d2(1.421413741f));
    h = fma2(h, t, d2(-0.284496736f));
    h = fma2(h, t, d2(0.254829592f));
    h = mul2(h, t);
    float2 pe = mul2(h, e);
    float2 E  = fma2(pe, d2(-1.0f), d2(1.0f));   // erf(z) >= 0
    float2 g  = mul2(ax, E);
    g = add2(x, g);
    return mul2(g, d2(0.5f));
}

// ---------------- kernel 1: fold BN into weights, detect args dtype ----------------
__global__ void prep_kernel(
    const float* __restrict__ W1, const float* __restrict__ g1, const float* __restrict__ b1,
    const float* __restrict__ m1, const float* __restrict__ v1,
    const float* __restrict__ W2, const float* __restrict__ g2, const float* __restrict__ b2,
    const float* __restrict__ m2, const float* __restrict__ v2,
    const float* __restrict__ W3, const float* __restrict__ g3, const float* __restrict__ b3,
    const float* __restrict__ m3, const float* __restrict__ v3,
    const float* __restrict__ W4, const float* __restrict__ g4, const float* __restrict__ b4,
    const float* __restrict__ m4, const float* __restrict__ v4,
    const float* __restrict__ Wc, const float* __restrict__ bc,
    const int*   __restrict__ args_i32)
{
    __shared__ float inv1[32], inv2[32], inv3[32], inv4[32];
    int t = threadIdx.x;
    if (t < 32) {
        float i1 = g1[t]*rsqrtf(v1[t]+EPSL); inv1[t]=i1; g_t1[t]=b1[t]-m1[t]*i1;
        float i2 = g2[t]*rsqrtf(v2[t]+EPSL); inv2[t]=i2; g_t2[t]=b2[t]-m2[t]*i2;
        float i3 = g3[t]*rsqrtf(v3[t]+EPSL); inv3[t]=i3; g_t3[t]=b3[t]-m3[t]*i3;
        float i4 = g4[t]*rsqrtf(v4[t]+EPSL); inv4[t]=i4; g_t4[t]=b4[t]-m4[t]*i4;
        g_wcA[t]=Wc[t]; g_wcB[t]=Wc[32+t]; g_wcC[t]=Wc[64+t];
        g_w1p[t]=W1[t*CT+64]*i1; g_w1a[t]=W1[t*CT+65]*i1; g_w1b[t]=W1[t*CT+66]*i1;
    }
    if (t < 3) g_bcv[t] = bc[t];
    if (t == 0) {
        // int64 little-endian: odd 32-bit words all zero (values < 2^31).
        int all_zero = 1;
        for (int i = 0; i < 128; i++) if (args_i32[2*i+1] != 0) { all_zero = 0; break; }
        g_args64 = all_zero;
    }
    __syncthreads();
    for (int idx = t; idx < 2048; idx += blockDim.x) {
        int r = idx >> 5, i = idx & 31;
        g_WPQ[idx] = (r < 32) ? W1[r*CT + i] * inv1[r]
                              : W1[(r-32)*CT + 32 + i] * inv1[r-32];
    }
    // duplicated-pair layer weights: idx = kk*64 + c*2 + {0,1}
    for (int idx = t; idx < 2048; idx += blockDim.x) {
        int kk = idx >> 6, c = (idx >> 1) & 31;
        g_W2d[idx] = W2[c*32+kk] * inv2[c];
        g_W3d[idx] = W3[c*32+kk] * inv3[c];
        g_W4d[idx] = W4[c*32+kk] * inv4[c];
    }
}

// ---------------- kernel 2: P/Q = folded-W1 @ If, written [b][n][c] ----------------
__global__ void pq_kernel(const float* __restrict__ If)
{
    __shared__ float wf[2048];
    __shared__ float tb[256*33];
    int tid  = threadIdx.x;
    int b    = blockIdx.x / NT;
    int tile = blockIdx.x % NT;
    int n0   = tile * 256;

    for (int idx = tid; idx < 2048; idx += 256) wf[idx] = g_WPQ[idx];

    int n = n0 + tid;
    float x[32];
    #pragma unroll
    for (int i = 0; i < 32; i++) x[i] = If[((size_t)b*32 + i)*NN + n];
    __syncthreads();

    size_t base = ((size_t)b*NN + n0) * 32;

    #pragma unroll
    for (int c = 0; c < 32; c++) {
        float acc = 0.f;
        #pragma unroll
        for (int i = 0; i < 32; i += 4) {
            float4 w = *(const float4*)&wf[c*32 + i];
            acc += w.x*x[i] + w.y*x[i+1] + w.z*x[i+2] + w.w*x[i+3];
        }
        tb[tid*33 + c] = acc;
    }
    __syncthreads();
    for (int idx = tid; idx < 8192; idx += 256)
        g_P[base + idx] = tb[(idx >> 5)*33 + (idx & 31)];
    __syncthreads();

    #pragma unroll
    for (int c = 0; c < 32; c++) {
        float acc = 0.f;
        #pragma unroll
        for (int i = 0; i < 32; i += 4) {
            float4 w = *(const float4*)&wf[(32+c)*32 + i];
            acc += w.x*x[i] + w.y*x[i+1] + w.z*x[i+2] + w.w*x[i+3];
        }
        tb[tid*33 + c] = acc;
    }
    __syncthreads();
    for (int idx = tid; idx < 8192; idx += 256)
        g_Q[base + idx] = tb[(idx >> 5)*33 + (idx & 31)];
}

// ---------------- fused MLP layer (FFMA2 path) ----------------
// thread (cg,sg) owns channels 4cg..4cg+3 and sample pairs sp(u)=2*sg+64u, u=0..3
template<bool ADD>
__device__ __forceinline__ void mlp_layer2(
    const float* __restrict__ src, float* __restrict__ dst,
    const float* __restrict__ Wd, const float* __restrict__ bias,
    const float* __restrict__ addsrc, int cg, int sg)
{
    int c0 = cg * 4;
    float4 bv = *(const float4*)&bias[c0];
    float2 acc0[4], acc1[4], acc2[4], acc3[4];
    #pragma unroll
    for (int u = 0; u < 4; u++) {
        acc0[u] = d2(bv.x); acc1[u] = d2(bv.y); acc2[u] = d2(bv.z); acc3[u] = d2(bv.w);
    }
    #pragma unroll
    for (int kk = 0; kk < 32; kk++) {
        float4 w01 = __ldg((const float4*)Wd + kk*16 + cg*2);      // {w0,w0,w1,w1}
        float4 w23 = __ldg((const float4*)Wd + kk*16 + cg*2 + 1);  // {w2,w2,w3,w3}
        float2 wd0 = make_float2(w01.x, w01.y);
        float2 wd1 = make_float2(w01.z, w01.w);
        float2 wd2 = make_float2(w23.x, w23.y);
        float2 wd3 = make_float2(w23.z, w23.w);
        const float* srow = src + kk*TS + sg*2;
        #pragma unroll
        for (int u = 0; u < 4; u++) {
            float2 a = *(const float2*)(srow + 64*u);
            acc0[u] = fma2(wd0, a, acc0[u]);
            acc1[u] = fma2(wd1, a, acc1[u]);
            acc2[u] = fma2(wd2, a, acc2[u]);
            acc3[u] = fma2(wd3, a, acc3[u]);
        }
    }
    #pragma unroll
    for (int u = 0; u < 4; u++) {
        int sp = sg*2 + 64*u;
        float2 v0 = acc0[u], v1 = acc1[u], v2 = acc2[u], v3 = acc3[u];
        if (ADD) {
            v0 = add2(v0, *(const float2*)&addsrc[(c0+0)*TS+sp]);
            v1 = add2(v1, *(const float2*)&addsrc[(c0+1)*TS+sp]);
            v2 = add2(v2, *(const float2*)&addsrc[(c0+2)*TS+sp]);
            v3 = add2(v3, *(const float2*)&addsrc[(c0+3)*TS+sp]);
        }
        *(float2*)&dst[(c0+0)*TS+sp] = gelu2(v0);
        *(float2*)&dst[(c0+1)*TS+sp] = gelu2(v1);
        *(float2*)&dst[(c0+2)*TS+sp] = gelu2(v2);
        *(float2*)&dst[(c0+3)*TS+sp] = gelu2(v3);
    }
}

// ---------------- kernel 3: main fused MLP over 256-sample tiles ----------------
__global__ void __launch_bounds__(256, 2) main_kernel(
    const float* __restrict__ Pf,
    const float* __restrict__ Of,
    const void*  __restrict__ args)
{
    extern __shared__ float sm[];
    float* buf0 = sm;             // 32x256
    float* buf1 = sm + 8192;
    float* buf2 = sm + 16384;
    int*   jj   = (int*)(sm + 24576);
    float* pfv  = sm + 24832;

    int bk   = blockIdx.x / NT;
    int tile = blockIdx.x % NT;
    int b = bk / NUMK, k = bk % NUMK;
    int n0 = tile * TS;
    int tid = threadIdx.x;
    int cg = tid >> 5, sg = tid & 31;
    int c0 = cg * 4;

    // stage 0: per-sample gather index + Pf gather
    {
        size_t ai = ((size_t)(b*NUMK + k))*NN + n0 + tid;
        long long j;
        if (g_args64) j = ((const long long*)args)[ai];
        else          j = ((const int*)args)[ai];
        jj[tid]  = (int)j;
        pfv[tid] = Pf[(size_t)b*NN + (int)j];
    }
    __syncthreads();

    // stage 1: z1 = P[n] + Q[j] + w1p*Pf[j] + w1a*Of0 + w1b*Of1 + t1 ; h1 = gelu(z1)
    {
        const float4* P4 = (const float4*)g_P;
        const float4* Q4 = (const float4*)g_Q;
        float4 wp = *(const float4*)&g_w1p[c0];
        float4 wa = *(const float4*)&g_w1a[c0];
        float4 wb = *(const float4*)&g_w1b[c0];
        float4 tt = *(const float4*)&g_t1[c0];
        const float* of0p = Of + ((size_t)(b*2+0)*NUMK + k)*NN + n0;
        const float* of1p = Of + ((size_t)(b*2+1)*NUMK + k)*NN + n0;
        #pragma unroll
        for (int u = 0; u < 4; u++) {
            int sp = sg*2 + 64*u;
            int n = n0 + sp;
            int j0 = jj[sp], j1 = jj[sp+1];
            float4 pA = __ldg(P4 + (size_t)(b*NN + n    )*8 + cg);
            float4 pB = __ldg(P4 + (size_t)(b*NN + n + 1)*8 + cg);
            float4 qA = __ldg(Q4 + (size_t)(b*NN + j0)*8 + cg);
            float4 qB = __ldg(Q4 + (size_t)(b*NN + j1)*8 + cg);
            float2 pf = *(const float2*)&pfv[sp];
            float2 o0 = *(const float2*)&of0p[sp];
            float2 o1 = *(const float2*)&of1p[sp];
            float2 z0, z1v, z2, z3;
            z0.x  = tt.x + pA.x + qA.x + wp.x*pf.x + wa.x*o0.x + wb.x*o1.x;
            z0.y  = tt.x + pB.x + qB.x + wp.x*pf.y + wa.x*o0.y + wb.x*o1.y;
            z1v.x = tt.y + pA.y + qA.y + wp.y*pf.x + wa.y*o0.x + wb.y*o1.x;
            z1v.y = tt.y + pB.y + qB.y + wp.y*pf.y + wa.y*o0.y + wb.y*o1.y;
            z2.x  = tt.z + pA.z + qA.z + wp.z*pf.x + wa.z*o0.x + wb.z*o1.x;
            z2.y  = tt.z + pB.z + qB.z + wp.z*pf.y + wa.z*o0.y + wb.z*o1.y;
            z3.x  = tt.w + pA.w + qA.w + wp.w*pf.x + wa.w*o0.x + wb.w*o1.x;
            z3.y  = tt.w + pB.w + qB.w + wp.w*pf.y + wa.w*o0.y + wb.w*o1.y;
            *(float2*)&buf0[(c0+0)*TS+sp] = gelu2(z0);
            *(float2*)&buf0[(c0+1)*TS+sp] = gelu2(z1v);
            *(float2*)&buf0[(c0+2)*TS+sp] = gelu2(z2);
            *(float2*)&buf0[(c0+3)*TS+sp] = gelu2(z3);
        }
    }
    __syncthreads();

    mlp_layer2<false>(buf0, buf1, g_W2d, g_t2, nullptr, cg, sg);  // h2 = gelu(bn2(W2 h1))
    __syncthreads();
    mlp_layer2<false>(buf1, buf2, g_W3d, g_t3, nullptr, cg, sg);  // l3 = gelu(bn3(W3 h2))
    __syncthreads();
    mlp_layer2<true >(buf2, buf0, g_W4d, g_t4, buf1,    cg, sg);  // XF = gelu(h2 + bn4(W4 l3))
    __syncthreads();

    // stage 5: head (3x32), U and Omega logits
    {
        int s = tid;
        float a = 0.f, be = 0.f, om = 0.f;
        #pragma unroll
        for (int c = 0; c < 32; c++) {
            float x = buf0[c*TS + s];
            a  += g_wcA[c]*x;
            be += g_wcB[c]*x;
            om += g_wcC[c]*x;
        }
        a  += g_bcv[0];
        be += g_bcv[1];
        om += g_bcv[2];
        float U = (a + 1.0f)*pfv[s] + be;
        size_t o = ((size_t)(b*NUMK + k))*NN + n0 + s;
        g_U[o]  = U;
        g_Om[o] = om;
    }
}

// ---------------- kernel 4: softmax over NUM + weighted sum ----------------
__global__ void epi_kernel(float* __restrict__ out)
{
    int gid = blockIdx.x * blockDim.x + threadIdx.x;
    if (gid >= BB*NN) return;
    int b = gid / NN, n = gid % NN;
    size_t base = (size_t)b*NUMK*NN + n;
    float om[NUMK];
    float m = -3.4e38f;
    #pragma unroll
    for (int k = 0; k < NUMK; k++) {
        om[k] = g_Om[base + (size_t)k*NN];
        m = fmaxf(m, om[k]);
    }
    float num = 0.f, den = 0.f;
    #pragma unroll
    for (int k = 0; k < NUMK; k++) {
        float e = expf(om[k] - m);
        den += e;
        num += e * g_U[base + (size_t)k*NN];
    }
    out[gid] = num / den;
}

// ---------------- launch ----------------
extern "C" void kernel_launch(void* const* d_in, const int* in_sizes, int n_in,
                              void* d_out, int out_size)
{
    const float* If = (const float*)d_in[0];
    const float* Pf = (const float*)d_in[1];
    const float* Of = (const float*)d_in[2];
    const void*  args = d_in[3];
    const float* W1 = (const float*)d_in[4];
    const float* g1 = (const float*)d_in[5];
    const float* b1 = (const float*)d_in[6];
    const float* m1 = (const float*)d_in[7];
    const float* v1 = (const float*)d_in[8];
    const float* W2 = (const float*)d_in[9];
    const float* g2 = (const float*)d_in[10];
    const float* b2 = (const float*)d_in[11];
    const float* m2 = (const float*)d_in[12];
    const float* v2 = (const float*)d_in[13];
    const float* W3 = (const float*)d_in[14];
    const float* g3 = (const float*)d_in[15];
    const float* b3 = (const float*)d_in[16];
    const float* m3 = (const float*)d_in[17];
    const float* v3 = (const float*)d_in[18];
    const float* W4 = (const float*)d_in[19];
    const float* g4 = (const float*)d_in[20];
    const float* b4 = (const float*)d_in[21];
    const float* m4 = (const float*)d_in[22];
    const float* v4 = (const float*)d_in[23];
    const float* Wc = (const float*)d_in[24];
    const float* bc = (const float*)d_in[25];

    prep_kernel<<<1, 256>>>(W1, g1, b1, m1, v1,
                            W2, g2, b2, m2, v2,
                            W3, g3, b3, m3, v3,
                            W4, g4, b4, m4, v4,
                            Wc, bc, (const int*)args);

    pq_kernel<<<BB*NT, 256>>>(If);

    const int dyn_smem = 25088 * 4;  // 100,352 B -> 2 blocks/SM
    cudaFuncSetAttribute(main_kernel, cudaFuncAttributeMaxDynamicSharedMemorySize, dyn_smem);
    main_kernel<<<BB*NUMK*NT, 256, dyn_smem>>>(Pf, Of, args);

    epi_kernel<<<(BB*NN + 255)/256, 256>>>((float*)d_out);
}

// round 3
// speedup vs baseline: 1.7067x; 1.7067x over previous
#include <cuda_runtime.h>

#define BB   2
#define CFI  32
#define HH   192
#define WWD  192
#define NN   (HH*WWD)        // 36864
#define NUMK 16
#define CT   67
#define EPSL 1e-5f
#define TS   256
#define NT   (NN/TS)         // 144

// ---------------- scratch (static device globals; no allocation) ----------------
__device__ float g_P[BB*NN*CFI];        // [b][n][c]  folded W1[:,0:32] @ If
__device__ float g_Q[BB*NN*CFI];        // [b][n][c]  folded W1[:,32:64] @ If
__device__ float g_U[BB*NUMK*NN];       // (Alpha+1)*Pfnum + Beta
__device__ float g_Om[BB*NUMK*NN];      // Omega logits

__device__ float g_WPQ[64*32];          // rows 0..31: P weights, 32..63: Q weights (BN-folded)
__device__ float g_w1p[32], g_w1a[32], g_w1b[32], g_t1[32];
__device__ float g_W2t[32*32], g_t2[32];   // transposed [k][c], BN-folded
__device__ float g_W3t[32*32], g_t3[32];
__device__ float g_W4t[32*32], g_t4[32];
__device__ float g_wcA[32], g_wcB[32], g_wcC[32];
__device__ float g_bcv[3];
__device__ int   g_args64;              // 1 if args buffer is int64, 0 if int32

__device__ __forceinline__ float frcp(float x) { float y; asm("rcp.approx.f32 %0, %1;" : "=f"(y) : "f"(x)); return y; }
__device__ __forceinline__ float fex2(float x) { float y; asm("ex2.approx.f32 %0, %1;" : "=f"(y) : "f"(x)); return y; }

// fast gelu: 0.5*(x + |x|*erf(|x|/sqrt2)), erf via A&S 7.1.26 (|eps|<=1.5e-7)
__device__ __forceinline__ float gelu_f(float x) {
    float ax = fabsf(x);
    float z  = ax * 0.70710678118654752f;
    float t  = frcp(fmaf(z, 0.3275911f, 1.0f));
    float e  = fex2(z * z * -1.4426950408889634f);
    float h  = fmaf(1.061405429f, t, -1.453152027f);
    h = fmaf(h, t, 1.421413741f);
    h = fmaf(h, t, -0.284496736f);
    h = fmaf(h, t, 0.254829592f);
    h = h * t;
    float E = fmaf(-h, e, 1.0f);          // erf(z), z >= 0
    return 0.5f * fmaf(ax, E, x);
}

// ---------------- kernel 1: fold BN into weights, detect args dtype ----------------
__global__ void prep_kernel(
    const float* __restrict__ W1, const float* __restrict__ g1, const float* __restrict__ b1,
    const float* __restrict__ m1, const float* __restrict__ v1,
    const float* __restrict__ W2, const float* __restrict__ g2, const float* __restrict__ b2,
    const float* __restrict__ m2, const float* __restrict__ v2,
    const float* __restrict__ W3, const float* __restrict__ g3, const float* __restrict__ b3,
    const float* __restrict__ m3, const float* __restrict__ v3,
    const float* __restrict__ W4, const float* __restrict__ g4, const float* __restrict__ b4,
    const float* __restrict__ m4, const float* __restrict__ v4,
    const float* __restrict__ Wc, const float* __restrict__ bc,
    const int*   __restrict__ args_i32)
{
    __shared__ float inv1[32], inv2[32], inv3[32], inv4[32];
    int t = threadIdx.x;
    if (t < 32) {
        float i1 = g1[t]*rsqrtf(v1[t]+EPSL); inv1[t]=i1; g_t1[t]=b1[t]-m1[t]*i1;
        float i2 = g2[t]*rsqrtf(v2[t]+EPSL); inv2[t]=i2; g_t2[t]=b2[t]-m2[t]*i2;
        float i3 = g3[t]*rsqrtf(v3[t]+EPSL); inv3[t]=i3; g_t3[t]=b3[t]-m3[t]*i3;
        float i4 = g4[t]*rsqrtf(v4[t]+EPSL); inv4[t]=i4; g_t4[t]=b4[t]-m4[t]*i4;
        g_wcA[t]=Wc[t]; g_wcB[t]=Wc[32+t]; g_wcC[t]=Wc[64+t];
        g_w1p[t]=W1[t*CT+64]*i1; g_w1a[t]=W1[t*CT+65]*i1; g_w1b[t]=W1[t*CT+66]*i1;
    }
    if (t < 3) g_bcv[t] = bc[t];
    if (t == 0) {
        // int64 little-endian: odd 32-bit words all zero (values < 2^31).
        int all_zero = 1;
        for (int i = 0; i < 128; i++) if (args_i32[2*i+1] != 0) { all_zero = 0; break; }
        g_args64 = all_zero;
    }
    __syncthreads();
    for (int idx = t; idx < 2048; idx += blockDim.x) {
        int r = idx >> 5, i = idx & 31;
        g_WPQ[idx] = (r < 32) ? W1[r*CT + i] * inv1[r]
                              : W1[(r-32)*CT + 32 + i] * inv1[r-32];
    }
    for (int idx = t; idx < 1024; idx += blockDim.x) {
        int kk = idx >> 5, c = idx & 31;
        g_W2t[idx] = W2[c*32+kk] * inv2[c];
        g_W3t[idx] = W3[c*32+kk] * inv3[c];
        g_W4t[idx] = W4[c*32+kk] * inv4[c];
    }
}

// ---------------- kernel 2: P/Q = folded-W1 @ If, written [b][n][c] ----------------
__global__ void pq_kernel(const float* __restrict__ If)
{
    __shared__ float wf[2048];
    __shared__ float tb[256*33];          // padded to kill STS bank conflicts
    int tid  = threadIdx.x;
    int b    = blockIdx.x / NT;
    int tile = blockIdx.x % NT;
    int n0   = tile * 256;

    for (int idx = tid; idx < 2048; idx += 256) wf[idx] = g_WPQ[idx];

    int n = n0 + tid;
    float x[32];
    #pragma unroll
    for (int i = 0; i < 32; i++) x[i] = If[((size_t)b*32 + i)*NN + n];
    __syncthreads();

    size_t base = ((size_t)b*NN + n0) * 32;

    // P
    #pragma unroll
    for (int c = 0; c < 32; c++) {
        float acc = 0.f;
        #pragma unroll
        for (int i = 0; i < 32; i += 4) {
            float4 w = *(const float4*)&wf[c*32 + i];
            acc += w.x*x[i] + w.y*x[i+1] + w.z*x[i+2] + w.w*x[i+3];
        }
        tb[tid*33 + c] = acc;
    }
    __syncthreads();
    for (int idx = tid; idx < 8192; idx += 256)
        g_P[base + idx] = tb[(idx >> 5)*33 + (idx & 31)];
    __syncthreads();

    // Q
    #pragma unroll
    for (int c = 0; c < 32; c++) {
        float acc = 0.f;
        #pragma unroll
        for (int i = 0; i < 32; i += 4) {
            float4 w = *(const float4*)&wf[(32+c)*32 + i];
            acc += w.x*x[i] + w.y*x[i+1] + w.z*x[i+2] + w.w*x[i+3];
        }
        tb[tid*33 + c] = acc;
    }
    __syncthreads();
    for (int idx = tid; idx < 8192; idx += 256)
        g_Q[base + idx] = tb[(idx >> 5)*33 + (idx & 31)];
}

// ---------------- fused MLP layer: dst[c][s] = gelu(Wt^T src + bias [+ addsrc]) ----------------
template<bool ADD>
__device__ __forceinline__ void mlp_layer(
    const float* __restrict__ src, float* __restrict__ dst,
    const float* __restrict__ Wt, const float* __restrict__ bias,
    const float* __restrict__ addsrc, int cg, int sg)
{
    int c0 = cg * 4;
    float4 tv = *(const float4*)&bias[c0];
    float acc0[8], acc1[8], acc2[8], acc3[8];
    #pragma unroll
    for (int u = 0; u < 8; u++) { acc0[u]=tv.x; acc1[u]=tv.y; acc2[u]=tv.z; acc3[u]=tv.w; }
    #pragma unroll
    for (int kk = 0; kk < 32; kk++) {
        float4 w = __ldg((const float4*)Wt + kk*8 + cg);   // broadcast, L1-hot
        #pragma unroll
        for (int u = 0; u < 8; u++) {
            float a = src[kk*TS + sg + 32*u];              // conflict-free LDS
            acc0[u] += w.x*a; acc1[u] += w.y*a; acc2[u] += w.z*a; acc3[u] += w.w*a;
        }
    }
    #pragma unroll
    for (int u = 0; u < 8; u++) {
        int s = sg + 32*u;
        float v0 = acc0[u], v1 = acc1[u], v2 = acc2[u], v3 = acc3[u];
        if (ADD) {
            v0 += addsrc[(c0+0)*TS+s]; v1 += addsrc[(c0+1)*TS+s];
            v2 += addsrc[(c0+2)*TS+s]; v3 += addsrc[(c0+3)*TS+s];
        }
        dst[(c0+0)*TS+s] = gelu_f(v0);
        dst[(c0+1)*TS+s] = gelu_f(v1);
        dst[(c0+2)*TS+s] = gelu_f(v2);
        dst[(c0+3)*TS+s] = gelu_f(v3);
    }
}

// ---------------- kernel 3: main fused MLP over 256-sample tiles ----------------
__global__ void __launch_bounds__(256, 2) main_kernel(
    const float* __restrict__ Pf,
    const float* __restrict__ Of,
    const void*  __restrict__ args)
{
    extern __shared__ float sm[];
    float* buf0 = sm;             // 32x256
    float* buf1 = sm + 8192;
    float* buf2 = sm + 16384;
    int*   jj   = (int*)(sm + 24576);
    float* pfv  = sm + 24832;

    int bk   = blockIdx.x / NT;
    int tile = blockIdx.x % NT;
    int b = bk / NUMK, k = bk % NUMK;
    int n0 = tile * TS;
    int tid = threadIdx.x;
    int cg = tid >> 5, sg = tid & 31;
    int c0 = cg * 4;

    // stage 0: per-sample gather index + Pf gather
    {
        size_t ai = ((size_t)(b*NUMK + k))*NN + n0 + tid;
        long long j;
        if (g_args64) j = ((const long long*)args)[ai];
        else          j = ((const int*)args)[ai];
        jj[tid]  = (int)j;
        pfv[tid] = Pf[(size_t)b*NN + (int)j];
    }
    __syncthreads();

    // stage 1: z1 = P[n] + Q[j] + w1p*Pf[j] + w1a*Of0 + w1b*Of1 + t1 ; h1 = gelu(z1)
    {
        const float4* P4 = (const float4*)g_P;
        const float4* Q4 = (const float4*)g_Q;
        float4 wp = *(const float4*)&g_w1p[c0];
        float4 wa = *(const float4*)&g_w1a[c0];
        float4 wb = *(const float4*)&g_w1b[c0];
        float4 tt = *(const float4*)&g_t1[c0];
        const float* of0p = Of + ((size_t)(b*2+0)*NUMK + k)*NN + n0;
        const float* of1p = Of + ((size_t)(b*2+1)*NUMK + k)*NN + n0;
        #pragma unroll
        for (int u = 0; u < 8; u++) {
            int s = sg + 32*u;
            int n = n0 + s;
            int j = jj[s];
            float4 p = __ldg(P4 + (size_t)(b*NN + n)*8 + cg);
            float4 q = __ldg(Q4 + (size_t)(b*NN + j)*8 + cg);
            float pf = pfv[s];
            float o0 = __ldg(of0p + s);
            float o1 = __ldg(of1p + s);
            float z0 = p.x + q.x + wp.x*pf + wa.x*o0 + wb.x*o1 + tt.x;
            float z1v= p.y + q.y + wp.y*pf + wa.y*o0 + wb.y*o1 + tt.y;
            float z2 = p.z + q.z + wp.z*pf + wa.z*o0 + wb.z*o1 + tt.z;
            float z3 = p.w + q.w + wp.w*pf + wa.w*o0 + wb.w*o1 + tt.w;
            buf0[(c0+0)*TS+s] = gelu_f(z0);
            buf0[(c0+1)*TS+s] = gelu_f(z1v);
            buf0[(c0+2)*TS+s] = gelu_f(z2);
            buf0[(c0+3)*TS+s] = gelu_f(z3);
        }
    }
    __syncthreads();

    mlp_layer<false>(buf0, buf1, g_W2t, g_t2, nullptr, cg, sg);  // h2 = gelu(bn2(W2 h1))
    __syncthreads();
    mlp_layer<false>(buf1, buf2, g_W3t, g_t3, nullptr, cg, sg);  // l3 = gelu(bn3(W3 h2))
    __syncthreads();
    mlp_layer<true >(buf2, buf0, g_W4t, g_t4, buf1,    cg, sg);  // XF = gelu(h2 + bn4(W4 l3))
    __syncthreads();

    // stage 5: head (3x32), U and Omega logits
    {
        int s = tid;
        float a = 0.f, be = 0.f, om = 0.f;
        #pragma unroll
        for (int c = 0; c < 32; c++) {
            float x = buf0[c*TS + s];
            a  += g_wcA[c]*x;
            be += g_wcB[c]*x;
            om += g_wcC[c]*x;
        }
        a  += g_bcv[0];
        be += g_bcv[1];
        om += g_bcv[2];
        float U = (a + 1.0f)*pfv[s] + be;
        size_t o = ((size_t)(b*NUMK + k))*NN + n0 + s;
        g_U[o]  = U;
        g_Om[o] = om;
    }
}

// ---------------- kernel 4: softmax over NUM + weighted sum ----------------
__global__ void epi_kernel(float* __restrict__ out)
{
    int gid = blockIdx.x * blockDim.x + threadIdx.x;
    if (gid >= BB*NN) return;
    int b = gid / NN, n = gid % NN;
    size_t base = (size_t)b*NUMK*NN + n;
    float om[NUMK];
    float m = -3.4e38f;
    #pragma unroll
    for (int k = 0; k < NUMK; k++) {
        om[k] = g_Om[base + (size_t)k*NN];
        m = fmaxf(m, om[k]);
    }
    float num = 0.f, den = 0.f;
    #pragma unroll
    for (int k = 0; k < NUMK; k++) {
        float e = fex2((om[k] - m) * 1.4426950408889634f);
        den += e;
        num += e * g_U[base + (size_t)k*NN];
    }
    out[gid] = num * frcp(den);
}

// ---------------- launch ----------------
extern "C" void kernel_launch(void* const* d_in, const int* in_sizes, int n_in,
                              void* d_out, int out_size)
{
    const float* If = (const float*)d_in[0];
    const float* Pf = (const float*)d_in[1];
    const float* Of = (const float*)d_in[2];
    const void*  args = d_in[3];
    const float* W1 = (const float*)d_in[4];
    const float* g1 = (const float*)d_in[5];
    const float* b1 = (const float*)d_in[6];
    const float* m1 = (const float*)d_in[7];
    const float* v1 = (const float*)d_in[8];
    const float* W2 = (const float*)d_in[9];
    const float* g2 = (const float*)d_in[10];
    const float* b2 = (const float*)d_in[11];
    const float* m2 = (const float*)d_in[12];
    const float* v2 = (const float*)d_in[13];
    const float* W3 = (const float*)d_in[14];
    const float* g3 = (const float*)d_in[15];
    const float* b3 = (const float*)d_in[16];
    const float* m3 = (const float*)d_in[17];
    const float* v3 = (const float*)d_in[18];
    const float* W4 = (const float*)d_in[19];
    const float* g4 = (const float*)d_in[20];
    const float* b4 = (const float*)d_in[21];
    const float* m4 = (const float*)d_in[22];
    const float* v4 = (const float*)d_in[23];
    const float* Wc = (const float*)d_in[24];
    const float* bc = (const float*)d_in[25];

    prep_kernel<<<1, 256>>>(W1, g1, b1, m1, v1,
                            W2, g2, b2, m2, v2,
                            W3, g3, b3, m3, v3,
                            W4, g4, b4, m4, v4,
                            Wc, bc, (const int*)args);

    pq_kernel<<<BB*NT, 256>>>(If);

    const int dyn_smem = 25088 * 4;  // 100,352 B -> 2 blocks/SM
    cudaFuncSetAttribute(main_kernel, cudaFuncAttributeMaxDynamicSharedMemorySize, dyn_smem);
    main_kernel<<<BB*NUMK*NT, 256, dyn_smem>>>(Pf, Of, args);

    epi_kernel<<<(BB*NN + 255)/256, 256>>>((float*)d_out);
}

// round 4
// speedup vs baseline: 1.7572x; 1.0296x over previous
#include <cuda_runtime.h>

#define BB   2
#define CFI  32
#define HH   192
#define WWD  192
#define NN   (HH*WWD)        // 36864
#define NUMK 16
#define CT   67
#define EPSL 1e-5f
#define TS   256
#define NT   (NN/TS)         // 144
#define SSTR 264             // smem activation row stride (floats): 264%32=8 -> conflict-free frags
#define WSTR 40              // smem weight row stride: 40%32=8 -> conflict-free B frags

// ---------------- scratch (static device globals; no allocation) ----------------
__device__ float g_P[BB*NN*CFI];        // [b][n][c]  folded W1[:,0:32] @ If
__device__ float g_Q[BB*NN*CFI];        // [b][n][c]  folded W1[:,32:64] @ If
__device__ float g_U[BB*NUMK*NN];       // (Alpha+1)*Pfnum + Beta
__device__ float g_Om[BB*NUMK*NN];      // Omega logits

__device__ float g_WPQ[64*32];          // rows 0..31: P weights, 32..63: Q weights (BN-folded)
__device__ float g_w1p[32], g_w1a[32], g_w1b[32], g_t1[32];
// tf32-split weights for layers 2..4: [0..1280) hi, [1280..2560) lo; layout [k][WSTR] (n in 0..31)
__device__ float g_W2s[2560], g_t2[32];
__device__ float g_W3s[2560], g_t3[32];
__device__ float g_W4s[2560], g_t4[32];
__device__ float g_wcA[32], g_wcB[32], g_wcC[32];
__device__ float g_bcv[3];
__device__ int   g_args64;              // 1 if args buffer is int64, 0 if int32

__device__ __forceinline__ float frcp(float x) { float y; asm("rcp.approx.f32 %0, %1;" : "=f"(y) : "f"(x)); return y; }
__device__ __forceinline__ float fex2(float x) { float y; asm("ex2.approx.f32 %0, %1;" : "=f"(y) : "f"(x)); return y; }
__device__ __forceinline__ float to_tf32(float x) {
    unsigned u; asm("cvt.rna.tf32.f32 %0, %1;" : "=r"(u) : "f"(x));
    return __uint_as_float(u);
}

// m16n8k8 tf32 MMA, row.col, fp32 accumulate in-place
__device__ __forceinline__ void mma8(float* d, float a0, float a1, float a2, float a3,
                                     float b0, float b1) {
    asm volatile(
        "mma.sync.aligned.m16n8k8.row.col.f32.tf32.tf32.f32 "
        "{%0,%1,%2,%3}, {%4,%5,%6,%7}, {%8,%9}, {%0,%1,%2,%3};"
        : "+f"(d[0]), "+f"(d[1]), "+f"(d[2]), "+f"(d[3])
        : "r"(__float_as_uint(a0)), "r"(__float_as_uint(a1)),
          "r"(__float_as_uint(a2)), "r"(__float_as_uint(a3)),
          "r"(__float_as_uint(b0)), "r"(__float_as_uint(b1)));
}

// fast gelu: 0.5*(x + |x|*erf(|x|/sqrt2)), erf via A&S 7.1.26 (|eps|<=1.5e-7)
__device__ __forceinline__ float gelu_f(float x) {
    float ax = fabsf(x);
    float z  = ax * 0.70710678118654752f;
    float t  = frcp(fmaf(z, 0.3275911f, 1.0f));
    float e  = fex2(z * z * -1.4426950408889634f);
    float h  = fmaf(1.061405429f, t, -1.453152027f);
    h = fmaf(h, t, 1.421413741f);
    h = fmaf(h, t, -0.284496736f);
    h = fmaf(h, t, 0.254829592f);
    h = h * t;
    float E = fmaf(-h, e, 1.0f);          // erf(z), z >= 0
    return 0.5f * fmaf(ax, E, x);
}

// ---------------- kernel 1: fold BN into weights, detect args dtype ----------------
__global__ void prep_kernel(
    const float* __restrict__ W1, const float* __restrict__ g1, const float* __restrict__ b1,
    const float* __restrict__ m1, const float* __restrict__ v1,
    const float* __restrict__ W2, const float* __restrict__ g2, const float* __restrict__ b2,
    const float* __restrict__ m2, const float* __restrict__ v2,
    const float* __restrict__ W3, const float* __restrict__ g3, const float* __restrict__ b3,
    const float* __restrict__ m3, const float* __restrict__ v3,
    const float* __restrict__ W4, const float* __restrict__ g4, const float* __restrict__ b4,
    const float* __restrict__ m4, const float* __restrict__ v4,
    const float* __restrict__ Wc, const float* __restrict__ bc,
    const int*   __restrict__ args_i32)
{
    __shared__ float inv1[32], inv2[32], inv3[32], inv4[32];
    int t = threadIdx.x;
    if (t < 32) {
        float i1 = g1[t]*rsqrtf(v1[t]+EPSL); inv1[t]=i1; g_t1[t]=b1[t]-m1[t]*i1;
        float i2 = g2[t]*rsqrtf(v2[t]+EPSL); inv2[t]=i2; g_t2[t]=b2[t]-m2[t]*i2;
        float i3 = g3[t]*rsqrtf(v3[t]+EPSL); inv3[t]=i3; g_t3[t]=b3[t]-m3[t]*i3;
        float i4 = g4[t]*rsqrtf(v4[t]+EPSL); inv4[t]=i4; g_t4[t]=b4[t]-m4[t]*i4;
        g_wcA[t]=Wc[t]; g_wcB[t]=Wc[32+t]; g_wcC[t]=Wc[64+t];
        g_w1p[t]=W1[t*CT+64]*i1; g_w1a[t]=W1[t*CT+65]*i1; g_w1b[t]=W1[t*CT+66]*i1;
    }
    if (t < 3) g_bcv[t] = bc[t];
    if (t == 0) {
        // int64 little-endian: odd 32-bit words all zero (values < 2^31).
        int all_zero = 1;
        for (int i = 0; i < 128; i++) if (args_i32[2*i+1] != 0) { all_zero = 0; break; }
        g_args64 = all_zero;
    }
    __syncthreads();
    for (int idx = t; idx < 2048; idx += blockDim.x) {
        int r = idx >> 5, i = idx & 31;
        g_WPQ[idx] = (r < 32) ? W1[r*CT + i] * inv1[r]
                              : W1[(r-32)*CT + 32 + i] * inv1[r-32];
    }
    // tf32-split B matrices, layout [k][WSTR] (value at [k][n] = W[n][k]*inv[n]), padded cols zeroed
    for (int idx = t; idx < 1280; idx += blockDim.x) {
        int kk = idx / WSTR, n = idx % WSTR;
        float w2 = 0.f, w3 = 0.f, w4 = 0.f;
        if (n < 32) {
            w2 = W2[n*32+kk] * inv2[n];
            w3 = W3[n*32+kk] * inv3[n];
            w4 = W4[n*32+kk] * inv4[n];
        }
        float h2 = to_tf32(w2), h3 = to_tf32(w3), h4 = to_tf32(w4);
        g_W2s[idx] = h2; g_W2s[1280+idx] = w2 - h2;
        g_W3s[idx] = h3; g_W3s[1280+idx] = w3 - h3;
        g_W4s[idx] = h4; g_W4s[1280+idx] = w4 - h4;
    }
}

// ---------------- kernel 2: P/Q = folded-W1 @ If, written [b][n][c] ----------------
__global__ void pq_kernel(const float* __restrict__ If)
{
    __shared__ float wf[2048];
    __shared__ float tb[256*33];          // padded to kill STS bank conflicts
    int tid  = threadIdx.x;
    int b    = blockIdx.x / NT;
    int tile = blockIdx.x % NT;
    int n0   = tile * 256;

    for (int idx = tid; idx < 2048; idx += 256) wf[idx] = g_WPQ[idx];

    int n = n0 + tid;
    float x[32];
    #pragma unroll
    for (int i = 0; i < 32; i++) x[i] = If[((size_t)b*32 + i)*NN + n];
    __syncthreads();

    size_t base = ((size_t)b*NN + n0) * 32;

    // P
    #pragma unroll
    for (int c = 0; c < 32; c++) {
        float acc = 0.f;
        #pragma unroll
        for (int i = 0; i < 32; i += 4) {
            float4 w = *(const float4*)&wf[c*32 + i];
            acc += w.x*x[i] + w.y*x[i+1] + w.z*x[i+2] + w.w*x[i+3];
        }
        tb[tid*33 + c] = acc;
    }
    __syncthreads();
    for (int idx = tid; idx < 8192; idx += 256)
        g_P[base + idx] = tb[(idx >> 5)*33 + (idx & 31)];
    __syncthreads();

    // Q
    #pragma unroll
    for (int c = 0; c < 32; c++) {
        float acc = 0.f;
        #pragma unroll
        for (int i = 0; i < 32; i += 4) {
            float4 w = *(const float4*)&wf[(32+c)*32 + i];
            acc += w.x*x[i] + w.y*x[i+1] + w.z*x[i+2] + w.w*x[i+3];
        }
        tb[tid*33 + c] = acc;
    }
    __syncthreads();
    for (int idx = tid; idx < 8192; idx += 256)
        g_Q[base + idx] = tb[(idx >> 5)*33 + (idx & 31)];
}

// ---------------- tensor-core MLP layer (3xTF32) ----------------
// src/dst: [32][SSTR] activations.  wsm: [k][WSTR] hi at 0, lo at +1280.
// D[256x32] = gelu( src^T(samples x ch) * B + bias [+ addsrc] )
// warp owns samples [32w, 32w+32): two m16 tiles; all 32 output channels (4 n-tiles).
template<bool ADD>
__device__ __forceinline__ void mma_layer(
    const float* __restrict__ src, float* __restrict__ dst,
    const float* __restrict__ wsm, const float* __restrict__ bias,
    const float* __restrict__ addsrc, int warp, int lane)
{
    int g  = lane >> 2;          // 0..7
    int tg = lane & 3;           // 0..3
    int m0 = warp * 32;

    float d[2][4][4];
    #pragma unroll
    for (int nt = 0; nt < 4; nt++) {
        float bA = __ldg(&bias[nt*8 + 2*tg]);
        float bBv = __ldg(&bias[nt*8 + 2*tg + 1]);
        #pragma unroll
        for (int mt = 0; mt < 2; mt++) {
            d[mt][nt][0] = bA; d[mt][nt][1] = bBv;
            d[mt][nt][2] = bA; d[mt][nt][3] = bBv;
        }
    }

    #pragma unroll
    for (int ks = 0; ks < 4; ks++) {
        int k0 = ks * 8;
        float ah[2][4], al[2][4];
        #pragma unroll
        for (int mt = 0; mt < 2; mt++) {
            int r = m0 + mt*16 + g;
            float x0 = src[(k0+tg  )*SSTR + r];
            float x1 = src[(k0+tg  )*SSTR + r + 8];
            float x2 = src[(k0+tg+4)*SSTR + r];
            float x3 = src[(k0+tg+4)*SSTR + r + 8];
            ah[mt][0] = to_tf32(x0); al[mt][0] = x0 - ah[mt][0];
            ah[mt][1] = to_tf32(x1); al[mt][1] = x1 - ah[mt][1];
            ah[mt][2] = to_tf32(x2); al[mt][2] = x2 - ah[mt][2];
            ah[mt][3] = to_tf32(x3); al[mt][3] = x3 - ah[mt][3];
        }
        #pragma unroll
        for (int nt = 0; nt < 4; nt++) {
            float bh0 = wsm[(k0+tg  )*WSTR + nt*8 + g];
            float bh1 = wsm[(k0+tg+4)*WSTR + nt*8 + g];
            float bl0 = wsm[1280 + (k0+tg  )*WSTR + nt*8 + g];
            float bl1 = wsm[1280 + (k0+tg+4)*WSTR + nt*8 + g];
            #pragma unroll
            for (int mt = 0; mt < 2; mt++) {
                mma8(d[mt][nt], ah[mt][0],ah[mt][1],ah[mt][2],ah[mt][3], bh0, bh1);
                mma8(d[mt][nt], al[mt][0],al[mt][1],al[mt][2],al[mt][3], bh0, bh1);
                mma8(d[mt][nt], ah[mt][0],ah[mt][1],ah[mt][2],ah[mt][3], bl0, bl1);
            }
        }
    }

    #pragma unroll
    for (int mt = 0; mt < 2; mt++) {
        int rA = m0 + mt*16 + g;
        int rB = rA + 8;
        #pragma unroll
        for (int nt = 0; nt < 4; nt++) {
            int nc = nt*8 + 2*tg;
            float v0 = d[mt][nt][0], v1 = d[mt][nt][1];
            float v2 = d[mt][nt][2], v3 = d[mt][nt][3];
            if (ADD) {
                v0 += addsrc[(nc  )*SSTR + rA];
                v1 += addsrc[(nc+1)*SSTR + rA];
                v2 += addsrc[(nc  )*SSTR + rB];
                v3 += addsrc[(nc+1)*SSTR + rB];
            }
            dst[(nc  )*SSTR + rA] = gelu_f(v0);
            dst[(nc+1)*SSTR + rA] = gelu_f(v1);
            dst[(nc  )*SSTR + rB] = gelu_f(v2);
            dst[(nc+1)*SSTR + rB] = gelu_f(v3);
        }
    }
}

// ---------------- kernel 3: main fused MLP over 256-sample tiles ----------------
__global__ void __launch_bounds__(256, 2) main_kernel(
    const float* __restrict__ Pf,
    const float* __restrict__ Of,
    const void*  __restrict__ args)
{
    extern __shared__ float sm[];
    float* buf0 = sm;                    // [32][SSTR]
    float* buf1 = sm + 32*SSTR;
    float* buf2 = sm + 64*SSTR;
    float* wsm  = sm + 96*SSTR;          // 2560 floats (hi|lo)
    int*   jj   = (int*)(sm + 96*SSTR + 2560);
    float* pfv  = sm + 96*SSTR + 2560 + 256;

    int bk   = blockIdx.x / NT;
    int tile = blockIdx.x % NT;
    int b = bk / NUMK, k = bk % NUMK;
    int n0 = tile * TS;
    int tid = threadIdx.x;
    int warp = tid >> 5, lane = tid & 31;
    int cg = warp, sg = lane;
    int c0 = cg * 4;

    // stage 0: per-sample gather index + Pf gather + stage layer-2 weights
    {
        size_t ai = ((size_t)(b*NUMK + k))*NN + n0 + tid;
        long long j;
        if (g_args64) j = ((const long long*)args)[ai];
        else          j = ((const int*)args)[ai];
        jj[tid]  = (int)j;
        pfv[tid] = Pf[(size_t)b*NN + (int)j];
    }
    for (int idx = tid; idx < 2560; idx += 256) wsm[idx] = g_W2s[idx];
    __syncthreads();

    // stage 1: z1 = P[n] + Q[j] + w1p*Pf[j] + w1a*Of0 + w1b*Of1 + t1 ; h1 = gelu(z1)
    {
        const float4* P4 = (const float4*)g_P;
        const float4* Q4 = (const float4*)g_Q;
        float4 wp = *(const float4*)&g_w1p[c0];
        float4 wa = *(const float4*)&g_w1a[c0];
        float4 wb = *(const float4*)&g_w1b[c0];
        float4 tt = *(const float4*)&g_t1[c0];
        const float* of0p = Of + ((size_t)(b*2+0)*NUMK + k)*NN + n0;
        const float* of1p = Of + ((size_t)(b*2+1)*NUMK + k)*NN + n0;
        #pragma unroll
        for (int u = 0; u < 8; u++) {
            int s = sg + 32*u;
            int n = n0 + s;
            int j = jj[s];
            float4 p = __ldg(P4 + (size_t)(b*NN + n)*8 + cg);
            float4 q = __ldg(Q4 + (size_t)(b*NN + j)*8 + cg);
            float pf = pfv[s];
            float o0 = __ldg(of0p + s);
            float o1 = __ldg(of1p + s);
            float z0 = p.x + q.x + wp.x*pf + wa.x*o0 + wb.x*o1 + tt.x;
            float z1v= p.y + q.y + wp.y*pf + wa.y*o0 + wb.y*o1 + tt.y;
            float z2 = p.z + q.z + wp.z*pf + wa.z*o0 + wb.z*o1 + tt.z;
            float z3 = p.w + q.w + wp.w*pf + wa.w*o0 + wb.w*o1 + tt.w;
            buf0[(c0+0)*SSTR+s] = gelu_f(z0);
            buf0[(c0+1)*SSTR+s] = gelu_f(z1v);
            buf0[(c0+2)*SSTR+s] = gelu_f(z2);
            buf0[(c0+3)*SSTR+s] = gelu_f(z3);
        }
    }
    __syncthreads();

    mma_layer<false>(buf0, buf1, wsm, g_t2, nullptr, warp, lane);   // h2
    __syncthreads();
    for (int idx = tid; idx < 2560; idx += 256) wsm[idx] = g_W3s[idx];
    __syncthreads();
    mma_layer<false>(buf1, buf2, wsm, g_t3, nullptr, warp, lane);   // l3
    __syncthreads();
    for (int idx = tid; idx < 2560; idx += 256) wsm[idx] = g_W4s[idx];
    __syncthreads();
    mma_layer<true >(buf2, buf0, wsm, g_t4, buf1, warp, lane);      // XF = gelu(h2 + bn4(W4 l3))
    __syncthreads();

    // stage 5: head (3x32), U and Omega logits
    {
        int s = tid;
        float a = 0.f, be = 0.f, om = 0.f;
        #pragma unroll
        for (int c = 0; c < 32; c++) {
            float x = buf0[c*SSTR + s];
            a  += g_wcA[c]*x;
            be += g_wcB[c]*x;
            om += g_wcC[c]*x;
        }
        a  += g_bcv[0];
        be += g_bcv[1];
        om += g_bcv[2];
        float U = (a + 1.0f)*pfv[s] + be;
        size_t o = ((size_t)(b*NUMK + k))*NN + n0 + s;
        g_U[o]  = U;
        g_Om[o] = om;
    }
}

// ---------------- kernel 4: softmax over NUM + weighted sum ----------------
__global__ void epi_kernel(float* __restrict__ out)
{
    int gid = blockIdx.x * blockDim.x + threadIdx.x;
    if (gid >= BB*NN) return;
    int b = gid / NN, n = gid % NN;
    size_t base = (size_t)b*NUMK*NN + n;
    float om[NUMK];
    float m = -3.4e38f;
    #pragma unroll
    for (int k = 0; k < NUMK; k++) {
        om[k] = g_Om[base + (size_t)k*NN];
        m = fmaxf(m, om[k]);
    }
    float num = 0.f, den = 0.f;
    #pragma unroll
    for (int k = 0; k < NUMK; k++) {
        float e = fex2((om[k] - m) * 1.4426950408889634f);
        den += e;
        num += e * g_U[base + (size_t)k*NN];
    }
    out[gid] = num * frcp(den);
}

// ---------------- launch ----------------
extern "C" void kernel_launch(void* const* d_in, const int* in_sizes, int n_in,
                              void* d_out, int out_size)
{
    const float* If = (const float*)d_in[0];
    const float* Pf = (const float*)d_in[1];
    const float* Of = (const float*)d_in[2];
    const void*  args = d_in[3];
    const float* W1 = (const float*)d_in[4];
    const float* g1 = (const float*)d_in[5];
    const float* b1 = (const float*)d_in[6];
    const float* m1 = (const float*)d_in[7];
    const float* v1 = (const float*)d_in[8];
    const float* W2 = (const float*)d_in[9];
    const float* g2 = (const float*)d_in[10];
    const float* b2 = (const float*)d_in[11];
    const float* m2 = (const float*)d_in[12];
    const float* v2 = (const float*)d_in[13];
    const float* W3 = (const float*)d_in[14];
    const float* g3 = (const float*)d_in[15];
    const float* b3 = (const float*)d_in[16];
    const float* m3 = (const float*)d_in[17];
    const float* v3 = (const float*)d_in[18];
    const float* W4 = (const float*)d_in[19];
    const float* g4 = (const float*)d_in[20];
    const float* b4 = (const float*)d_in[21];
    const float* m4 = (const float*)d_in[22];
    const float* v4 = (const float*)d_in[23];
    const float* Wc = (const float*)d_in[24];
    const float* bc = (const float*)d_in[25];

    prep_kernel<<<1, 256>>>(W1, g1, b1, m1, v1,
                            W2, g2, b2, m2, v2,
                            W3, g3, b3, m3, v3,
                            W4, g4, b4, m4, v4,
                            Wc, bc, (const int*)args);

    pq_kernel<<<BB*NT, 256>>>(If);

    // smem: 3 act buffers (32*264) + weights (2560) + jj (256) + pfv (256)
    const int dyn_smem = (96*SSTR + 2560 + 256 + 256) * 4;   // 113,664 B -> 2 blocks/SM
    cudaFuncSetAttribute(main_kernel, cudaFuncAttributeMaxDynamicSharedMemorySize, dyn_smem);
    main_kernel<<<BB*NUMK*NT, 256, dyn_smem>>>(Pf, Of, args);

    epi_kernel<<<(BB*NN + 255)/256, 256>>>((float*)d_out);
}

// round 5
// speedup vs baseline: 3.0122x; 1.7142x over previous
#include <cuda_runtime.h>
#include <cstdint>

#define BB   2
#define CFI  32
#define HH   192
#define WWD  192
#define NN   (HH*WWD)        // 36864
#define NUMK 16
#define CT   67
#define EPSL 1e-5f
#define TS   256
#define NT   (NN/TS)         // 144

// ---------------- scratch (static device globals; no allocation) ----------------
__device__ float g_P[BB*NN*CFI];        // [b][n][c]
__device__ float g_Q[BB*NN*CFI];        // [b][n][c]
__device__ float g_U[BB*NUMK*NN];
__device__ float g_Om[BB*NUMK*NN];

__device__ float g_WPQ[64*32];
__device__ float g_w1p[32], g_w1a[32], g_w1b[32], g_t1[32];
// packed bf16x2 weights per layer: [k2][32] uint32, hi at [0,512), lo at [512,1024)
// wpack[k2][n] = {bf16(W[n][2k2]*inv), bf16(W[n][2k2+1]*inv)} (lo half = even k)
__device__ unsigned g_W2p[1024];
__device__ unsigned g_W3p[1024];
__device__ unsigned g_W4p[1024];
__device__ float g_t2[32], g_t3[32], g_t4[32];
__device__ float g_wcA[32], g_wcB[32], g_wcC[32];
__device__ float g_bcv[3];
__device__ int   g_args64;

__device__ __forceinline__ float frcp(float x) { float y; asm("rcp.approx.f32 %0, %1;" : "=f"(y) : "f"(x)); return y; }
__device__ __forceinline__ float fex2(float x) { float y; asm("ex2.approx.f32 %0, %1;" : "=f"(y) : "f"(x)); return y; }

__device__ __forceinline__ unsigned pack_bf16(float lo, float hi) {
    unsigned r; asm("cvt.rn.bf16x2.f32 %0, %1, %2;" : "=r"(r) : "f"(hi), "f"(lo)); return r;
}
__device__ __forceinline__ float bf_lo(unsigned p) { return __uint_as_float(p << 16); }
__device__ __forceinline__ float bf_hi(unsigned p) { return __uint_as_float(p & 0xffff0000u); }

// m16n8k16 bf16 MMA, row.col, fp32 accumulate in-place
__device__ __forceinline__ void mma16(float* d, unsigned a0, unsigned a1, unsigned a2, unsigned a3,
                                      unsigned b0, unsigned b1) {
    asm volatile(
        "mma.sync.aligned.m16n8k16.row.col.f32.bf16.bf16.f32 "
        "{%0,%1,%2,%3}, {%4,%5,%6,%7}, {%8,%9}, {%0,%1,%2,%3};"
        : "+f"(d[0]), "+f"(d[1]), "+f"(d[2]), "+f"(d[3])
        : "r"(a0), "r"(a1), "r"(a2), "r"(a3), "r"(b0), "r"(b1));
}

// fast gelu: 0.5*(x + |x|*erf(|x|/sqrt2)), erf via A&S 7.1.26 (|eps|<=1.5e-7)
__device__ __forceinline__ float gelu_f(float x) {
    float ax = fabsf(x);
    float z  = ax * 0.70710678118654752f;
    float t  = frcp(fmaf(z, 0.3275911f, 1.0f));
    float e  = fex2(z * z * -1.4426950408889634f);
    float h  = fmaf(1.061405429f, t, -1.453152027f);
    h = fmaf(h, t, 1.421413741f);
    h = fmaf(h, t, -0.284496736f);
    h = fmaf(h, t, 0.254829592f);
    h = h * t;
    float E = fmaf(-h, e, 1.0f);
    return 0.5f * fmaf(ax, E, x);
}

// ---------------- kernel 1: fold BN, pack bf16 weights, detect args dtype ----------------
__global__ void prep_kernel(
    const float* __restrict__ W1, const float* __restrict__ g1, const float* __restrict__ b1,
    const float* __restrict__ m1, const float* __restrict__ v1,
    const float* __restrict__ W2, const float* __restrict__ g2, const float* __restrict__ b2,
    const float* __restrict__ m2, const float* __restrict__ v2,
    const float* __restrict__ W3, const float* __restrict__ g3, const float* __restrict__ b3,
    const float* __restrict__ m3, const float* __restrict__ v3,
    const float* __restrict__ W4, const float* __restrict__ g4, const float* __restrict__ b4,
    const float* __restrict__ m4, const float* __restrict__ v4,
    const float* __restrict__ Wc, const float* __restrict__ bc,
    const int*   __restrict__ args_i32)
{
    __shared__ float inv1[32], inv2[32], inv3[32], inv4[32];
    int t = threadIdx.x;
    if (t < 32) {
        float i1 = g1[t]*rsqrtf(v1[t]+EPSL); inv1[t]=i1; g_t1[t]=b1[t]-m1[t]*i1;
        float i2 = g2[t]*rsqrtf(v2[t]+EPSL); inv2[t]=i2; g_t2[t]=b2[t]-m2[t]*i2;
        float i3 = g3[t]*rsqrtf(v3[t]+EPSL); inv3[t]=i3; g_t3[t]=b3[t]-m3[t]*i3;
        float i4 = g4[t]*rsqrtf(v4[t]+EPSL); inv4[t]=i4; g_t4[t]=b4[t]-m4[t]*i4;
        g_wcA[t]=Wc[t]; g_wcB[t]=Wc[32+t]; g_wcC[t]=Wc[64+t];
        g_w1p[t]=W1[t*CT+64]*i1; g_w1a[t]=W1[t*CT+65]*i1; g_w1b[t]=W1[t*CT+66]*i1;
    }
    if (t < 3) g_bcv[t] = bc[t];
    if (t == 0) {
        int all_zero = 1;
        for (int i = 0; i < 128; i++) if (args_i32[2*i+1] != 0) { all_zero = 0; break; }
        g_args64 = all_zero;
    }
    __syncthreads();
    for (int idx = t; idx < 2048; idx += blockDim.x) {
        int r = idx >> 5, i = idx & 31;
        g_WPQ[idx] = (r < 32) ? W1[r*CT + i] * inv1[r]
                              : W1[(r-32)*CT + 32 + i] * inv1[r-32];
    }
    // packed bf16 split weights: idx = k2*32 + n
    for (int idx = t; idx < 512; idx += blockDim.x) {
        int k2 = idx >> 5, n = idx & 31;
        float w0, w1, h0, h1;
        unsigned ph;
        w0 = W2[n*32 + 2*k2]*inv2[n]; w1 = W2[n*32 + 2*k2 + 1]*inv2[n];
        ph = pack_bf16(w0, w1); h0 = bf_lo(ph); h1 = bf_hi(ph);
        g_W2p[idx] = ph; g_W2p[512+idx] = pack_bf16(w0-h0, w1-h1);
        w0 = W3[n*32 + 2*k2]*inv3[n]; w1 = W3[n*32 + 2*k2 + 1]*inv3[n];
        ph = pack_bf16(w0, w1); h0 = bf_lo(ph); h1 = bf_hi(ph);
        g_W3p[idx] = ph; g_W3p[512+idx] = pack_bf16(w0-h0, w1-h1);
        w0 = W4[n*32 + 2*k2]*inv4[n]; w1 = W4[n*32 + 2*k2 + 1]*inv4[n];
        ph = pack_bf16(w0, w1); h0 = bf_lo(ph); h1 = bf_hi(ph);
        g_W4p[idx] = ph; g_W4p[512+idx] = pack_bf16(w0-h0, w1-h1);
    }
}

// ---------------- kernel 2: P/Q = folded-W1 @ If, written [b][n][c] ----------------
__global__ void pq_kernel(const float* __restrict__ If)
{
    __shared__ float wf[2048];
    __shared__ float tb[256*33];
    int tid  = threadIdx.x;
    int b    = blockIdx.x / NT;
    int tile = blockIdx.x % NT;
    int n0   = tile * 256;

    for (int idx = tid; idx < 2048; idx += 256) wf[idx] = g_WPQ[idx];

    int n = n0 + tid;
    float x[32];
    #pragma unroll
    for (int i = 0; i < 32; i++) x[i] = If[((size_t)b*32 + i)*NN + n];
    __syncthreads();

    size_t base = ((size_t)b*NN + n0) * 32;

    #pragma unroll
    for (int c = 0; c < 32; c++) {
        float acc = 0.f;
        #pragma unroll
        for (int i = 0; i < 32; i += 4) {
            float4 w = *(const float4*)&wf[c*32 + i];
            acc += w.x*x[i] + w.y*x[i+1] + w.z*x[i+2] + w.w*x[i+3];
        }
        tb[tid*33 + c] = acc;
    }
    __syncthreads();
    for (int idx = tid; idx < 8192; idx += 256)
        g_P[base + idx] = tb[(idx >> 5)*33 + (idx & 31)];
    __syncthreads();

    #pragma unroll
    for (int c = 0; c < 32; c++) {
        float acc = 0.f;
        #pragma unroll
        for (int i = 0; i < 32; i += 4) {
            float4 w = *(const float4*)&wf[(32+c)*32 + i];
            acc += w.x*x[i] + w.y*x[i+1] + w.z*x[i+2] + w.w*x[i+3];
        }
        tb[tid*33 + c] = acc;
    }
    __syncthreads();
    for (int idx = tid; idx < 8192; idx += 256)
        g_Q[base + idx] = tb[(idx >> 5)*33 + (idx & 31)];
}

// ---------------- register-resident MLP layer (3xBF16 mma) ----------------
// x layout: x[mt*16 + nt*4 + e], channel = 8*nt + 2*tg + (e&1),
//           sample row = 32*warp + 16*mt + g + 8*(e>>1)
template<bool ADD>
__device__ __forceinline__ void layer_reg(
    const float* xin, float* xout,
    const unsigned* __restrict__ wp, const float* __restrict__ bias,
    const float* resid, int g, int tg)
{
    // split-pack activations to bf16 hi/lo
    unsigned ah[16], al[16];
    #pragma unroll
    for (int mt = 0; mt < 2; mt++)
    #pragma unroll
    for (int nt = 0; nt < 4; nt++) {
        int base = mt*16 + nt*4;
        #pragma unroll
        for (int hh = 0; hh < 2; hh++) {
            float x0 = xin[base + 2*hh], x1 = xin[base + 2*hh + 1];
            unsigned ph = pack_bf16(x0, x1);
            float l0 = x0 - bf_lo(ph);
            float l1 = x1 - bf_hi(ph);
            ah[(mt*4 + nt)*2 + hh] = ph;
            al[(mt*4 + nt)*2 + hh] = pack_bf16(l0, l1);
        }
    }
    // init accumulators with bias
    float d[32];
    #pragma unroll
    for (int nt = 0; nt < 4; nt++) {
        float2 bv = __ldg((const float2*)bias + 4*nt + tg);
        #pragma unroll
        for (int mt = 0; mt < 2; mt++) {
            d[mt*16 + nt*4 + 0] = bv.x; d[mt*16 + nt*4 + 1] = bv.y;
            d[mt*16 + nt*4 + 2] = bv.x; d[mt*16 + nt*4 + 3] = bv.y;
        }
    }
    // mma mainloop: 2 k-steps x 4 n-tiles x 2 m-tiles x 3 passes
    #pragma unroll
    for (int ks = 0; ks < 2; ks++) {
        #pragma unroll
        for (int nt = 0; nt < 4; nt++) {
            unsigned bh0 = __ldg(wp +        (ks*8 + tg    )*32 + 8*nt + g);
            unsigned bh1 = __ldg(wp +        (ks*8 + tg + 4)*32 + 8*nt + g);
            unsigned bl0 = __ldg(wp + 512 +  (ks*8 + tg    )*32 + 8*nt + g);
            unsigned bl1 = __ldg(wp + 512 +  (ks*8 + tg + 4)*32 + 8*nt + g);
            #pragma unroll
            for (int mt = 0; mt < 2; mt++) {
                int ia  = (mt*4 + 2*ks    )*2;   // a0,a1 source (k 0..15 of this ks)
                int ia2 = (mt*4 + 2*ks + 1)*2;   // a2,a3 source (k 8..)
                float* dd = d + mt*16 + nt*4;
                mma16(dd, ah[ia], ah[ia+1], ah[ia2], ah[ia2+1], bh0, bh1);
                mma16(dd, al[ia], al[ia+1], al[ia2], al[ia2+1], bh0, bh1);
                mma16(dd, ah[ia], ah[ia+1], ah[ia2], ah[ia2+1], bl0, bl1);
            }
        }
    }
    #pragma unroll
    for (int i = 0; i < 32; i++) {
        float v = d[i];
        if (ADD) v += resid[i];
        xout[i] = gelu_f(v);
    }
}

// ---------------- kernel 3: main fused MLP, fully register-resident ----------------
__global__ void __launch_bounds__(256) main_kernel(
    const float* __restrict__ Pf,
    const float* __restrict__ Of,
    const void*  __restrict__ args)
{
    int bk   = blockIdx.x / NT;
    int tile = blockIdx.x % NT;
    int b = bk / NUMK, k = bk % NUMK;
    int n0 = tile * TS;
    int tid = threadIdx.x;
    int w = tid >> 5, lane = tid & 31;
    int g = lane >> 2, tg = lane & 3;

    float xa[32], xb[32];
    float pfs[4];

    // stage 1: h1 in D-frag register layout
    {
        float2 w1p2[4], w1a2[4], w1b2[4], t12[4];
        #pragma unroll
        for (int q = 0; q < 4; q++) {
            w1p2[q] = __ldg((const float2*)g_w1p + 4*q + tg);
            w1a2[q] = __ldg((const float2*)g_w1a + 4*q + tg);
            w1b2[q] = __ldg((const float2*)g_w1b + 4*q + tg);
            t12[q]  = __ldg((const float2*)g_t1  + 4*q + tg);
        }
        const float* of0p = Of + ((size_t)(b*2+0)*NUMK + k)*NN;
        const float* of1p = Of + ((size_t)(b*2+1)*NUMK + k)*NN;
        int use64 = g_args64;
        #pragma unroll
        for (int mt = 0; mt < 2; mt++)
        #pragma unroll
        for (int hh = 0; hh < 2; hh++) {
            int s = 32*w + 16*mt + 8*hh + g;
            int n = n0 + s;
            size_t ai = ((size_t)(b*NUMK + k))*NN + n;
            int j;
            if (use64) j = (int)__ldg((const long long*)args + ai);
            else       j = __ldg((const int*)args + ai);
            float pf = __ldg(Pf + (size_t)b*NN + j);
            pfs[mt*2 + hh] = pf;
            float o0 = __ldg(of0p + n);
            float o1 = __ldg(of1p + n);
            const float2* P2 = (const float2*)g_P + (size_t)(b*NN + n)*16 + tg;
            const float2* Q2 = (const float2*)g_Q + (size_t)(b*NN + j)*16 + tg;
            #pragma unroll
            for (int q = 0; q < 4; q++) {
                float2 p  = __ldg(P2 + 4*q);
                float2 qv = __ldg(Q2 + 4*q);
                float z0 = p.x + qv.x + w1p2[q].x*pf + w1a2[q].x*o0 + w1b2[q].x*o1 + t12[q].x;
                float z1 = p.y + qv.y + w1p2[q].y*pf + w1a2[q].y*o0 + w1b2[q].y*o1 + t12[q].y;
                xa[mt*16 + q*4 + 2*hh]     = gelu_f(z0);
                xa[mt*16 + q*4 + 2*hh + 1] = gelu_f(z1);
            }
        }
    }

    layer_reg<false>(xa, xb, g_W2p, g_t2, nullptr, g, tg);   // h2 = xb
    layer_reg<false>(xb, xa, g_W3p, g_t3, nullptr, g, tg);   // l3 = xa
    layer_reg<true >(xa, xa, g_W4p, g_t4, xb,      g, tg);   // XF = gelu(h2 + bn4(W4 l3))

    // head: 3x32 dot per sample, reduce across the 4 tg-lanes of each sample
    {
        float2 wA2[4], wB2[4], wC2[4];
        #pragma unroll
        for (int nt = 0; nt < 4; nt++) {
            wA2[nt] = __ldg((const float2*)g_wcA + 4*nt + tg);
            wB2[nt] = __ldg((const float2*)g_wcB + 4*nt + tg);
            wC2[nt] = __ldg((const float2*)g_wcC + 4*nt + tg);
        }
        float bc0 = g_bcv[0], bc1 = g_bcv[1], bc2 = g_bcv[2];
        size_t obase = ((size_t)(b*NUMK + k))*NN + n0;
        #pragma unroll
        for (int mt = 0; mt < 2; mt++)
        #pragma unroll
        for (int hh = 0; hh < 2; hh++) {
            float a = 0.f, be = 0.f, om = 0.f;
            #pragma unroll
            for (int nt = 0; nt < 4; nt++) {
                float x0 = xa[mt*16 + nt*4 + 2*hh];
                float x1 = xa[mt*16 + nt*4 + 2*hh + 1];
                a  += wA2[nt].x*x0 + wA2[nt].y*x1;
                be += wB2[nt].x*x0 + wB2[nt].y*x1;
                om += wC2[nt].x*x0 + wC2[nt].y*x1;
            }
            a  += __shfl_xor_sync(0xffffffffu, a, 1);
            a  += __shfl_xor_sync(0xffffffffu, a, 2);
            be += __shfl_xor_sync(0xffffffffu, be, 1);
            be += __shfl_xor_sync(0xffffffffu, be, 2);
            om += __shfl_xor_sync(0xffffffffu, om, 1);
            om += __shfl_xor_sync(0xffffffffu, om, 2);
            if (tg == 0) {
                int s = 32*w + 16*mt + 8*hh + g;
                float U = (a + bc0 + 1.0f)*pfs[mt*2 + hh] + (be + bc1);
                g_U[obase + s]  = U;
                g_Om[obase + s] = om + bc2;
            }
        }
    }
}

// ---------------- kernel 4: softmax over NUM + weighted sum ----------------
__global__ void epi_kernel(float* __restrict__ out)
{
    int gid = blockIdx.x * blockDim.x + threadIdx.x;
    if (gid >= BB*NN) return;
    int b = gid / NN, n = gid % NN;
    size_t base = (size_t)b*NUMK*NN + n;
    float om[NUMK];
    float m = -3.4e38f;
    #pragma unroll
    for (int k = 0; k < NUMK; k++) {
        om[k] = g_Om[base + (size_t)k*NN];
        m = fmaxf(m, om[k]);
    }
    float num = 0.f, den = 0.f;
    #pragma unroll
    for (int k = 0; k < NUMK; k++) {
        float e = fex2((om[k] - m) * 1.4426950408889634f);
        den += e;
        num += e * g_U[base + (size_t)k*NN];
    }
    out[gid] = num * frcp(den);
}

// ---------------- launch ----------------
extern "C" void kernel_launch(void* const* d_in, const int* in_sizes, int n_in,
                              void* d_out, int out_size)
{
    const float* If = (const float*)d_in[0];
    const float* Pf = (const float*)d_in[1];
    const float* Of = (const float*)d_in[2];
    const void*  args = d_in[3];
    const float* W1 = (const float*)d_in[4];
    const float* g1 = (const float*)d_in[5];
    const float* b1 = (const float*)d_in[6];
    const float* m1 = (const float*)d_in[7];
    const float* v1 = (const float*)d_in[8];
    const float* W2 = (const float*)d_in[9];
    const float* g2 = (const float*)d_in[10];
    const float* b2 = (const float*)d_in[11];
    const float* m2 = (const float*)d_in[12];
    const float* v2 = (const float*)d_in[13];
    const float* W3 = (const float*)d_in[14];
    const float* g3 = (const float*)d_in[15];
    const float* b3 = (const float*)d_in[16];
    const float* m3 = (const float*)d_in[17];
    const float* v3 = (const float*)d_in[18];
    const float* W4 = (const float*)d_in[19];
    const float* g4 = (const float*)d_in[20];
    const float* b4 = (const float*)d_in[21];
    const float* m4 = (const float*)d_in[22];
    const float* v4 = (const float*)d_in[23];
    const float* Wc = (const float*)d_in[24];
    const float* bc = (const float*)d_in[25];

    prep_kernel<<<1, 256>>>(W1, g1, b1, m1, v1,
                            W2, g2, b2, m2, v2,
                            W3, g3, b3, m3, v3,
                            W4, g4, b4, m4, v4,
                            Wc, bc, (const int*)args);

    pq_kernel<<<BB*NT, 256>>>(If);

    main_kernel<<<BB*NUMK*NT, 256>>>(Pf, Of, args);

    epi_kernel<<<(BB*NN + 255)/256, 256>>>((float*)d_out);
}